// round 17
// baseline (speedup 1.0000x reference)
#include <cuda_runtime.h>
#include <math.h>

#define BB   2
#define SS   768
#define DDIM 1024
#define HH   16
#define HDIM 64
#define NQh  8
#define NF   16
#define BHn  (BB*HH)     // 32
#define MM   (BB*SS)     // 1536
#define PROW 772         // 772 % 32 == 4 -> conflict-free ldmatrix rows
#define SPITCH 20
#define KPITCH 84        // 84 % 32 == 20 -> conflict-free
#define VPITCH 68        // 68 % 32 == 4  -> conflict-free
#define ENTN 831
#define ATHREADS 512

// ---------------- scratch ----------------------------------------------------
__device__ float g_Q[BHn*SS*HDIM];      // [bh][s][d]
__device__ float g_K[BHn*SS*HDIM];      // [bh][s][d]
__device__ float g_V[BHn*SS*HDIM];      // [bh][d][s]  (TRANSPOSED)
__device__ float g_fQ[BHn*SS*NF];
__device__ float g_fK[BHn*SS*NF];
__device__ float g_att[MM*DDIM];        // tf32-valued floats (rounded at attn)
__device__ float g_Ar[3*MM*DDIM];       // rna-rounded q/k/v
__device__ float g_Wt[4*DDIM*DDIM];     // transposed + rna-rounded weights [z][n][k]

// ---------------- helpers ----------------------------------------------------
__device__ __forceinline__ unsigned f2tf32(float f) {
    unsigned u;
    asm("cvt.rna.tf32.f32 %0, %1;" : "=r"(u) : "f"(f));
    return u;
}

__device__ __forceinline__ void mma_tf32(float& c0, float& c1, float& c2, float& c3,
                                         unsigned a0, unsigned a1, unsigned a2, unsigned a3,
                                         unsigned b0, unsigned b1) {
    asm volatile("mma.sync.aligned.m16n8k8.row.col.f32.tf32.tf32.f32 "
                 "{%0,%1,%2,%3}, {%4,%5,%6,%7}, {%8,%9}, {%0,%1,%2,%3};\n"
                 : "+f"(c0), "+f"(c1), "+f"(c2), "+f"(c3)
                 : "r"(a0), "r"(a1), "r"(a2), "r"(a3), "r"(b0), "r"(b1));
}

__device__ __forceinline__ void ldsm_x4(unsigned& r0, unsigned& r1,
                                        unsigned& r2, unsigned& r3, unsigned addr) {
    asm volatile("ldmatrix.sync.aligned.m8n8.x4.shared.b16 {%0,%1,%2,%3}, [%4];"
                 : "=r"(r0), "=r"(r1), "=r"(r2), "=r"(r3) : "r"(addr));
}

__device__ __forceinline__ void red_add_v4(float* p, float x, float y, float z, float w) {
    asm volatile("red.global.add.v4.f32 [%0], {%1,%2,%3,%4};"
                 :: "l"(p), "f"(x), "f"(y), "f"(z), "f"(w) : "memory");
}

__device__ __forceinline__ void red_add_v2(float* p, float x, float y) {
    asm volatile("red.global.add.v2.f32 [%0], {%1,%2};"
                 :: "l"(p), "f"(x), "f"(y) : "memory");
}

__device__ __forceinline__ void cpa16(unsigned dst, const void* src) {
    asm volatile("cp.async.cg.shared.global [%0], [%1], 16;"
                 :: "r"(dst), "l"(src) : "memory");
}
#define CPA_COMMIT() asm volatile("cp.async.commit_group;" ::: "memory")
#define CPA_WAIT1()  asm volatile("cp.async.wait_group 1;" ::: "memory")
#define CPA_WAIT0()  asm volatile("cp.async.wait_group 0;" ::: "memory")

// ============================================================================
// tf32 GEMM core, cp.async staging. A[m][k] from APTR (pre-rounded), B[n][k]
// from BPTR (pre-rounded, transposed). 128x128 tile, 8 warps.
// ============================================================================
#define GEMM_CPA(APTR, BPTR, NCHUNK, KBASE)                                      \
    float acc[4][4][4] = {};                                                     \
    int tid = threadIdx.x;                                                       \
    int wid = tid >> 5, lane = tid & 31;                                         \
    int wm = wid & 1, wnw = wid >> 1;                                            \
    int a_row = lane & 15, a_koff = (lane >> 4) * 4;                             \
    int b_nr  = (lane & 7) + ((lane >> 4) << 3);                                 \
    int b_koff = ((lane >> 3) & 1) * 4;                                          \
    int srow = tid >> 2, sc4 = (tid & 3) * 4;                                    \
    unsigned aBs[2] = {(unsigned)__cvta_generic_to_shared(As0),                  \
                       (unsigned)__cvta_generic_to_shared(As1)};                 \
    unsigned bBs[2] = {(unsigned)__cvta_generic_to_shared(Bs0),                  \
                       (unsigned)__cvta_generic_to_shared(Bs1)};                 \
    {   int kg = (KBASE);                                                        \
        cpa16(aBs[0] + (srow * SPITCH + sc4) * 4,                                \
              (APTR) + (size_t)(row0 + srow) * DDIM + kg + sc4);                 \
        cpa16(aBs[0] + ((srow + 64) * SPITCH + sc4) * 4,                         \
              (APTR) + (size_t)(row0 + 64 + srow) * DDIM + kg + sc4);            \
        cpa16(bBs[0] + (srow * SPITCH + sc4) * 4,                                \
              (BPTR) + (size_t)(col0 + srow) * DDIM + kg + sc4);                 \
        cpa16(bBs[0] + ((srow + 64) * SPITCH + sc4) * 4,                         \
              (BPTR) + (size_t)(col0 + 64 + srow) * DDIM + kg + sc4);            \
        CPA_COMMIT();                                                            \
    }                                                                            \
    for (int ch = 0; ch < (NCHUNK); ch++) {                                      \
        int buf = ch & 1;                                                        \
        if (ch + 1 < (NCHUNK)) {                                                 \
            int kg = (KBASE) + (ch + 1) * 16; int nb = buf ^ 1;                  \
            cpa16(aBs[nb] + (srow * SPITCH + sc4) * 4,                           \
                  (APTR) + (size_t)(row0 + srow) * DDIM + kg + sc4);             \
            cpa16(aBs[nb] + ((srow + 64) * SPITCH + sc4) * 4,                    \
                  (APTR) + (size_t)(row0 + 64 + srow) * DDIM + kg + sc4);        \
            cpa16(bBs[nb] + (srow * SPITCH + sc4) * 4,                           \
                  (BPTR) + (size_t)(col0 + srow) * DDIM + kg + sc4);             \
            cpa16(bBs[nb] + ((srow + 64) * SPITCH + sc4) * 4,                    \
                  (BPTR) + (size_t)(col0 + 64 + srow) * DDIM + kg + sc4);        \
            CPA_COMMIT(); CPA_WAIT1();                                           \
        } else { CPA_WAIT0(); }                                                  \
        __syncthreads();                                                         \
        unsigned aB = aBs[buf], bB = bBs[buf];                                   \
        _Pragma("unroll")                                                        \
        for (int ks = 0; ks < 2; ks++) {                                         \
            int kc = ks * 8;                                                     \
            unsigned af[4][4];                                                   \
            _Pragma("unroll")                                                    \
            for (int mt = 0; mt < 4; mt++)                                       \
                ldsm_x4(af[mt][0], af[mt][1], af[mt][2], af[mt][3],              \
                    aB + ((wm * 64 + mt * 16 + a_row) * SPITCH + kc + a_koff) * 4);\
            unsigned bf[4][2];                                                   \
            _Pragma("unroll")                                                    \
            for (int p = 0; p < 2; p++)                                          \
                ldsm_x4(bf[2 * p][0], bf[2 * p][1], bf[2 * p + 1][0],            \
                        bf[2 * p + 1][1],                                        \
                    bB + ((wnw * 32 + p * 16 + b_nr) * SPITCH + kc + b_koff) * 4);\
            _Pragma("unroll")                                                    \
            for (int mt = 0; mt < 4; mt++)                                       \
                _Pragma("unroll")                                                \
                for (int nt = 0; nt < 4; nt++)                                   \
                    mma_tf32(acc[mt][nt][0], acc[mt][nt][1],                     \
                             acc[mt][nt][2], acc[mt][nt][3],                     \
                             af[mt][0], af[mt][1], af[mt][2], af[mt][3],         \
                             bf[nt][0], bf[nt][1]);                              \
        }                                                                        \
        __syncthreads();                                                         \
    }

// ---------------- pre: round q/k/v -> g_Ar -----------------------------------
__global__ __launch_bounds__(256) void around_kernel(const float* __restrict__ q,
                                                     const float* __restrict__ k,
                                                     const float* __restrict__ v) {
    size_t idx = (size_t)blockIdx.x * 256 + threadIdx.x;
    size_t n = (size_t)MM * DDIM / 4;
    if (idx >= 3 * n) return;
    int which = (int)(idx / n);
    size_t off = idx % n;
    const float4* src = (const float4*)((which == 0) ? q : (which == 1) ? k : v);
    float4 f = src[off];
    float4 o;
    o.x = __uint_as_float(f2tf32(f.x));
    o.y = __uint_as_float(f2tf32(f.y));
    o.z = __uint_as_float(f2tf32(f.z));
    o.w = __uint_as_float(f2tf32(f.w));
    ((float4*)(g_Ar + (size_t)which * MM * DDIM))[off] = o;
}

// ---------------- pre: transpose + round weights -> g_Wt ---------------------
__global__ __launch_bounds__(256) void wtrans_kernel(
        const float* __restrict__ Wq, const float* __restrict__ Wk,
        const float* __restrict__ Wv, const float* __restrict__ Wo) {
    __shared__ float t[32][33];
    int z = blockIdx.z;
    const float* W = (z == 0) ? Wq : (z == 1) ? Wk : (z == 2) ? Wv : Wo;
    int n0 = blockIdx.x * 32, k0 = blockIdx.y * 32;
    #pragma unroll
    for (int j = 0; j < 4; j++)
        t[threadIdx.y + j * 8][threadIdx.x] =
            W[(size_t)(k0 + threadIdx.y + j * 8) * DDIM + n0 + threadIdx.x];
    __syncthreads();
    #pragma unroll
    for (int j = 0; j < 4; j++)
        g_Wt[((size_t)z * DDIM + n0 + threadIdx.y + j * 8) * DDIM + k0 + threadIdx.x] =
            __uint_as_float(f2tf32(t[threadIdx.x][threadIdx.y + j * 8]));
}

// ---------------- fused QKV projection (cp.async core) -----------------------
__global__ __launch_bounds__(256, 2) void proj_kernel(
        const float* __restrict__ bq, const float* __restrict__ bk,
        const float* __restrict__ bv) {
    int which = blockIdx.z;
    const float* A    = g_Ar + (size_t)which * MM * DDIM;
    const float* Bp   = g_Wt + (size_t)which * DDIM * DDIM;
    const float* bias = (which == 0) ? bq : (which == 1) ? bk : bv;
    float*       out  = (which == 0) ? g_Q : (which == 1) ? g_K : g_V;

    __shared__ unsigned As0[128 * SPITCH], As1[128 * SPITCH];
    __shared__ unsigned Bs0[128 * SPITCH], Bs1[128 * SPITCH];
    int row0 = blockIdx.y * 128, col0 = blockIdx.x * 128;

    GEMM_CPA(A, Bp, DDIM / 16, 0)

    int g = lane >> 2, tg = lane & 3;
    #pragma unroll
    for (int mt = 0; mt < 4; mt++)
        #pragma unroll
        for (int nt = 0; nt < 4; nt++) {
            int gm = row0 + wm * 64 + mt * 16 + g;
            int gn = col0 + wnw * 32 + nt * 8 + tg * 2;
            #pragma unroll
            for (int hrow = 0; hrow < 2; hrow++) {
                int m = gm + hrow * 8;
                int b = m / SS, s = m % SS;
                int h = gn >> 6, d = gn & 63;
                if (which == 2) {   // V transposed: [bh][d][s]
                    #pragma unroll
                    for (int j = 0; j < 2; j++)
                        out[((size_t)(b * HH + h) * HDIM + d + j) * SS + s] =
                            acc[mt][nt][hrow * 2 + j] + bias[gn + j];
                } else {            // Q/K: [bh][s][d]
                    float2 st;
                    st.x = acc[mt][nt][hrow * 2]     + bias[gn];
                    st.y = acc[mt][nt][hrow * 2 + 1] + bias[gn + 1];
                    *(float2*)&out[((size_t)(b * HH + h) * SS + s) * HDIM + d] = st;
                }
            }
        }
}

// ---------------- outproj, split-K=3, cp.async core --------------------------
__global__ __launch_bounds__(256, 2) void outproj_kernel(const float* __restrict__ bo,
                                                         float* __restrict__ out) {
    __shared__ unsigned As0[128 * SPITCH], As1[128 * SPITCH];
    __shared__ unsigned Bs0[128 * SPITCH], Bs1[128 * SPITCH];
    int row0 = blockIdx.y * 128, col0 = blockIdx.x * 128;
    int z = blockIdx.z;
    int kbase = (z == 0) ? 0 : (z == 1) ? 352 : 688;
    int nch   = (z == 0) ? 22 : 21;
    const float* Bp = g_Wt + (size_t)3 * DDIM * DDIM;

    GEMM_CPA(g_att, Bp, nch, kbase)

    int g = lane >> 2, tg = lane & 3;
    bool addb = (z == 0);
    #pragma unroll
    for (int mt = 0; mt < 4; mt++)
        #pragma unroll
        for (int nt = 0; nt < 4; nt++) {
            int gm = row0 + wm * 64 + mt * 16 + g;
            int gn = col0 + wnw * 32 + nt * 8 + tg * 2;
            #pragma unroll
            for (int hrow = 0; hrow < 2; hrow++) {
                int m = gm + hrow * 8;
                float x = acc[mt][nt][hrow * 2]     + (addb ? bo[gn]     : 0.f);
                float y = acc[mt][nt][hrow * 2 + 1] + (addb ? bo[gn + 1] : 0.f);
                red_add_v2(&out[(size_t)m * DDIM + gn], x, y);
            }
        }
}

// ---------------- quantum features (warp-per-row) + output zero-fill ---------
__global__ __launch_bounds__(256) void qfeat_kernel(
        const float* __restrict__ qmapW, const float* __restrict__ qmapb,
        const float* __restrict__ qw, const float* __restrict__ ph,
        const float* __restrict__ es_ptr, float* __restrict__ outbuf) {
    {
        int gtid = blockIdx.x * blockDim.x + threadIdx.x;
        int n1 = MM * DDIM / 4;
        int n2 = BB * SS * SS / 4;
        if (gtid < n1)
            ((float4*)outbuf)[gtid] = make_float4(0.f, 0.f, 0.f, 0.f);
        int g2 = gtid - n1;
        if (g2 >= 0 && g2 < n2)
            ((float4*)(outbuf + (size_t)MM * DDIM))[g2] = make_float4(0.f, 0.f, 0.f, 0.f);
    }
    int gw   = (blockIdx.x * blockDim.x + threadIdx.x) >> 5;
    int lane = threadIdx.x & 31;
    if (gw >= 2 * BHn * SS) return;
    int side = gw / (BHn * SS);
    int r    = gw % (BHn * SS);
    int h    = (r / SS) % HH;
    const float* row = ((side == 0) ? g_Q : g_K) + (size_t)r * HDIM;
    float rv0 = row[lane], rv1 = row[lane + 32];

    float mydot = 0.f;
    #pragma unroll
    for (int n = 0; n < NQh; n++) {
        float p = rv0 * qmapW[lane * NQh + n] + rv1 * qmapW[(lane + 32) * NQh + n];
        #pragma unroll
        for (int o = 16; o; o >>= 1) p += __shfl_xor_sync(0xffffffffu, p, o);
        if (lane == n) mydot = p;
    }
    if (lane < NQh) {
        float a = tanhf(mydot + qmapb[lane]);
        float s, c;
        if (side == 0) {
            float mix = 1.f / (1.f + __expf(-*es_ptr));
            float w = (1.f / (1.f + __expf(-qw[h * NQh + lane]))) * (1.0f / NQh) * mix;
            sincosf(a + ph[h * NQh + lane], &s, &c);
            g_fQ[(size_t)r * NF + lane]       = w * c;
            g_fQ[(size_t)r * NF + NQh + lane] = w * s;
        } else {
            sincosf(a, &s, &c);
            g_fK[(size_t)r * NF + lane]       = c;
            g_fK[(size_t)r * NF + NQh + lane] = s;
        }
    }
}

// ---------------- fused attention (512 thr; quantum-skip for far tiles) -----
__global__ __launch_bounds__(ATHREADS) void attn_kernel(const float* __restrict__ es_ptr,
                                                        float* __restrict__ out2) {
    extern __shared__ float P[];                       // [64][PROW]
    unsigned* Ks   = (unsigned*)(P + 64 * PROW);       // phase 1
    float*    entT = (float*)(Ks + 64 * KPITCH);       // phase 1 LUT
    unsigned* Vs0  = (unsigned*)(P + 64 * PROW);       // phase 3
    unsigned* Vs1  = Vs0 + 64 * VPITCH;

    int bh = blockIdx.y;
    int b = bh >> 4, h = bh & 15;
    int ic = blockIdx.x;
    int i0 = ic * 64;
    const float* Qp  = g_Q  + (size_t)bh * SS * HDIM;
    const float* Kp  = g_K  + (size_t)bh * SS * HDIM;
    const float* Vtp = g_V  + (size_t)bh * HDIM * SS;  // [d][s]
    const float* Fqp = g_fQ + (size_t)bh * SS * NF;
    const float* Fkp = g_fK + (size_t)bh * SS * NF;
    float* o2p = out2 + (size_t)b * SS * SS;

    int tid = threadIdx.x;
    int wid = tid >> 5, lane = tid & 31;
    int wm = wid & 3, wn = wid >> 2;                   // 4m x 4n
    int g = lane >> 2, tg = lane & 3;
    int a_row = lane & 15, a_koff = (lane >> 4) * 4;
    int b_nr  = (lane & 7) + ((lane >> 4) << 3);
    int b_koff = ((lane >> 3) & 1) * 4;
    unsigned PBase   = (unsigned)__cvta_generic_to_shared(P);
    unsigned KsBase  = (unsigned)__cvta_generic_to_shared(Ks);
    unsigned VsBase0 = (unsigned)__cvta_generic_to_shared(Vs0);
    unsigned VsBase1 = (unsigned)__cvta_generic_to_shared(Vs1);

    float es  = *es_ptr;
    float mix = 1.f / (1.f + __expf(-es));
    float ca  = (1.f - mix) * 0.125f;

    for (int t = tid; t < ENTN; t += ATHREADS)
        entT[t] = __expf(-0.1f * fabsf((float)(i0 - 767 + t)));

    int sF_r = tid >> 2, sF_c4 = (tid & 3) * 4;

    {
        #pragma unroll
        for (int it = 0; it < 2; it++) {
            int fid = tid + ATHREADS * it;
            int r = fid >> 4, c4 = (fid & 15) * 4;
            float4 f = *(const float4*)&Qp[(size_t)(i0 + r) * HDIM + c4];
            *(uint4*)&Ks[r * KPITCH + c4] =
                make_uint4(f2tf32(ca * f.x), f2tf32(ca * f.y),
                           f2tf32(ca * f.z), f2tf32(ca * f.w));
        }
        if (tid < 256) {
            float4 f = *(const float4*)&Fqp[(size_t)(i0 + sF_r) * NF + sF_c4];
            *(uint4*)&Ks[sF_r * KPITCH + 64 + sF_c4] =
                make_uint4(f2tf32(f.x), f2tf32(f.y), f2tf32(f.z), f2tf32(f.w));
        }
    }
    __syncthreads();
    unsigned afr[10][4];
    #pragma unroll
    for (int s = 0; s < 10; s++) {
        int r = wm * 16 + g, c = s * 8 + tg;
        afr[s][0] = Ks[r * KPITCH + c];
        afr[s][1] = Ks[(r + 8) * KPITCH + c];
        afr[s][2] = Ks[r * KPITCH + c + 4];
        afr[s][3] = Ks[(r + 8) * KPITCH + c + 4];
    }
    __syncthreads();

    // ---- phase 1: scores over 12 K-chunks (depth-2 prefetch) ---------------
    float4 rcA[2], rqA, rcB[2], rqB;
    {
        #pragma unroll
        for (int it = 0; it < 2; it++) {
            int fid = tid + ATHREADS * it;
            int r = fid >> 4, c4 = (fid & 15) * 4;
            rcA[it] = *(const float4*)&Kp[(size_t)r * HDIM + c4];
        }
        if (tid < 256)
            rqA = *(const float4*)&Fkp[(size_t)sF_r * NF + sF_c4];
        #pragma unroll
        for (int it = 0; it < 2; it++) {
            int fid = tid + ATHREADS * it;
            int r = fid >> 4, c4 = (fid & 15) * 4;
            *(uint4*)&Ks[r * KPITCH + c4] =
                make_uint4(f2tf32(rcA[it].x), f2tf32(rcA[it].y),
                           f2tf32(rcA[it].z), f2tf32(rcA[it].w));
        }
        if (tid < 256)
            *(uint4*)&Ks[sF_r * KPITCH + 64 + sF_c4] =
                make_uint4(f2tf32(rqA.x), f2tf32(rqA.y), f2tf32(rqA.z), f2tf32(rqA.w));
        #pragma unroll
        for (int it = 0; it < 2; it++) {
            int fid = tid + ATHREADS * it;
            int r = fid >> 4, c4 = (fid & 15) * 4;
            rcA[it] = *(const float4*)&Kp[(size_t)(64 + r) * HDIM + c4];
        }
        if (tid < 256)
            rqA = *(const float4*)&Fkp[(size_t)(64 + sF_r) * NF + sF_c4];
        __syncthreads();
    }
    for (int jc = 0; jc < 12; jc++) {
        int j0 = jc * 64;
        int dj = jc - ic;
        bool useQ = (dj <= 2) && (dj >= -2);    // ent <= 2.5e-6 beyond this
        if (jc + 2 < 12) {
            int jn = j0 + 128;
            #pragma unroll
            for (int it = 0; it < 2; it++) {
                int fid = tid + ATHREADS * it;
                int r = fid >> 4, c4 = (fid & 15) * 4;
                rcB[it] = *(const float4*)&Kp[(size_t)(jn + r) * HDIM + c4];
            }
            if (tid < 256)
                rqB = *(const float4*)&Fkp[(size_t)(jn + sF_r) * NF + sF_c4];
        }
        float accC[2][4] = {}, accQ[2][4] = {};
        #pragma unroll
        for (int s = 0; s < 8; s++) {           // classical: always
            int kc = s * 8;
            unsigned bf[2][2];
            ldsm_x4(bf[0][0], bf[0][1], bf[1][0], bf[1][1],
                    KsBase + ((wn * 16 + b_nr) * KPITCH + kc + b_koff) * 4);
            #pragma unroll
            for (int nt = 0; nt < 2; nt++)
                mma_tf32(accC[nt][0], accC[nt][1], accC[nt][2], accC[nt][3],
                         afr[s][0], afr[s][1], afr[s][2], afr[s][3],
                         bf[nt][0], bf[nt][1]);
        }
        if (useQ) {                             // quantum: near tiles only
            #pragma unroll
            for (int s = 8; s < 10; s++) {
                int kc = s * 8;
                unsigned bf[2][2];
                ldsm_x4(bf[0][0], bf[0][1], bf[1][0], bf[1][1],
                        KsBase + ((wn * 16 + b_nr) * KPITCH + kc + b_koff) * 4);
                #pragma unroll
                for (int nt = 0; nt < 2; nt++)
                    mma_tf32(accQ[nt][0], accQ[nt][1], accQ[nt][2], accQ[nt][3],
                             afr[s][0], afr[s][1], afr[s][2], afr[s][3],
                             bf[nt][0], bf[nt][1]);
            }
        }
        #pragma unroll
        for (int nt = 0; nt < 2; nt++) {
            int r  = wm * 16 + g;
            int cl = wn * 16 + nt * 8 + tg * 2;
            #pragma unroll
            for (int hrow = 0; hrow < 2; hrow++) {
                int rr = r + hrow * 8;
                float2 st;
                if (useQ) {
                    int base = rr + 767 - j0 - cl;
                    st.x = accC[nt][hrow * 2]     + entT[base]     * accQ[nt][hrow * 2];
                    st.y = accC[nt][hrow * 2 + 1] + entT[base - 1] * accQ[nt][hrow * 2 + 1];
                } else {
                    st.x = accC[nt][hrow * 2];
                    st.y = accC[nt][hrow * 2 + 1];
                }
                *(float2*)&P[rr * PROW + j0 + cl] = st;
            }
        }
        __syncthreads();
        if (jc + 1 < 12) {
            #pragma unroll
            for (int it = 0; it < 2; it++) {
                int fid = tid + ATHREADS * it;
                int r = fid >> 4, c4 = (fid & 15) * 4;
                *(uint4*)&Ks[r * KPITCH + c4] =
                    make_uint4(f2tf32(rcA[it].x), f2tf32(rcA[it].y),
                               f2tf32(rcA[it].z), f2tf32(rcA[it].w));
            }
            if (tid < 256)
                *(uint4*)&Ks[sF_r * KPITCH + 64 + sF_c4] =
                    make_uint4(f2tf32(rqA.x), f2tf32(rqA.y),
                               f2tf32(rqA.z), f2tf32(rqA.w));
        }
        __syncthreads();
        rcA[0] = rcB[0]; rcA[1] = rcB[1]; rqA = rqB;
    }

    float4 vA[2], vB[2];
    #pragma unroll
    for (int it = 0; it < 2; it++) {
        int fid = tid + ATHREADS * it;
        int d = fid >> 4, c4 = (fid & 15) * 4;
        vA[it] = *(const float4*)&Vtp[(size_t)d * SS + c4];
    }

    for (int rr = wid; rr < 64; rr += 16) {
        float4* row4 = (float4*)(P + rr * PROW);
        float4 v[6];
        float m = -1e30f;
        #pragma unroll
        for (int u = 0; u < 6; u++) {
            v[u] = row4[lane + u * 32];
            m = fmaxf(m, fmaxf(fmaxf(v[u].x, v[u].y), fmaxf(v[u].z, v[u].w)));
        }
        #pragma unroll
        for (int o = 16; o; o >>= 1) m = fmaxf(m, __shfl_xor_sync(0xffffffffu, m, o));
        float ssum = 0.f;
        #pragma unroll
        for (int u = 0; u < 6; u++) {
            v[u].x = __expf(v[u].x - m); v[u].y = __expf(v[u].y - m);
            v[u].z = __expf(v[u].z - m); v[u].w = __expf(v[u].w - m);
            ssum += (v[u].x + v[u].y) + (v[u].z + v[u].w);
        }
        #pragma unroll
        for (int o = 16; o; o >>= 1) ssum += __shfl_xor_sync(0xffffffffu, ssum, o);
        float inv = __frcp_rn(ssum);
        float* o2row = o2p + (size_t)(i0 + rr) * SS;
        #pragma unroll
        for (int u = 0; u < 6; u++) {
            float4 t;
            t.x = __uint_as_float(f2tf32(v[u].x * inv));
            t.y = __uint_as_float(f2tf32(v[u].y * inv));
            t.z = __uint_as_float(f2tf32(v[u].z * inv));
            t.w = __uint_as_float(f2tf32(v[u].w * inv));
            row4[lane + u * 32] = t;
            red_add_v4(o2row + (lane + u * 32) * 4,
                       t.x * (1.0f / HH), t.y * (1.0f / HH),
                       t.z * (1.0f / HH), t.w * (1.0f / HH));
        }
    }
    __syncthreads();

    float acc[2][4] = {};
    {
        #pragma unroll
        for (int it = 0; it < 2; it++) {
            int fid = tid + ATHREADS * it;
            int d = fid >> 4, c4 = (fid & 15) * 4;
            *(uint4*)&Vs0[d * VPITCH + c4] =
                make_uint4(f2tf32(vA[it].x), f2tf32(vA[it].y),
                           f2tf32(vA[it].z), f2tf32(vA[it].w));
        }
        #pragma unroll
        for (int it = 0; it < 2; it++) {
            int fid = tid + ATHREADS * it;
            int d = fid >> 4, c4 = (fid & 15) * 4;
            vA[it] = *(const float4*)&Vtp[(size_t)d * SS + 64 + c4];
        }
        __syncthreads();
    }
    for (int c = 0; c < 12; c++) {
        int k0 = c * 64;
        unsigned curB = (c & 1) ? VsBase1 : VsBase0;
        unsigned* nxt = (c & 1) ? Vs0 : Vs1;
        if (c + 2 < 12) {
            int kn = k0 + 128;
            #pragma unroll
            for (int it = 0; it < 2; it++) {
                int fid = tid + ATHREADS * it;
                int d = fid >> 4, c4 = (fid & 15) * 4;
                vB[it] = *(const float4*)&Vtp[(size_t)d * SS + kn + c4];
            }
        }
        #pragma unroll
        for (int s = 0; s < 8; s++) {
            int kc = s * 8;
            unsigned af[4];
            ldsm_x4(af[0], af[1], af[2], af[3],
                    PBase + ((wm * 16 + a_row) * PROW + k0 + kc + a_koff) * 4);
            unsigned bf[2][2];
            ldsm_x4(bf[0][0], bf[0][1], bf[1][0], bf[1][1],
                    curB + ((wn * 16 + b_nr) * VPITCH + kc + b_koff) * 4);
            #pragma unroll
            for (int nt = 0; nt < 2; nt++)
                mma_tf32(acc[nt][0], acc[nt][1], acc[nt][2], acc[nt][3],
                         af[0], af[1], af[2], af[3], bf[nt][0], bf[nt][1]);
        }
        if (c + 1 < 12) {
            #pragma unroll
            for (int it = 0; it < 2; it++) {
                int fid = tid + ATHREADS * it;
                int d = fid >> 4, c4 = (fid & 15) * 4;
                *(uint4*)&nxt[d * VPITCH + c4] =
                    make_uint4(f2tf32(vA[it].x), f2tf32(vA[it].y),
                               f2tf32(vA[it].z), f2tf32(vA[it].w));
            }
        }
        __syncthreads();
        vA[0] = vB[0]; vA[1] = vB[1];
    }
    // epilogue -> g_att, tf32-rounded so outproj's raw cp.async == rna path
    #pragma unroll
    for (int nt = 0; nt < 2; nt++) {
        int r = wm * 16 + g;
        int d0 = wn * 16 + nt * 8 + tg * 2;
        #pragma unroll
        for (int hrow = 0; hrow < 2; hrow++) {
            int s_ = i0 + r + hrow * 8;
            float2 st;
            st.x = __uint_as_float(f2tf32(acc[nt][hrow * 2]));
            st.y = __uint_as_float(f2tf32(acc[nt][hrow * 2 + 1]));
            *(float2*)&g_att[(size_t)(b * SS + s_) * DDIM + h * HDIM + d0] = st;
        }
    }
}

// ---------------- launch -----------------------------------------------------
extern "C" void kernel_launch(void* const* d_in, const int* in_sizes, int n_in,
                              void* d_out, int out_size) {
    const float* query = (const float*)d_in[0];
    const float* key   = (const float*)d_in[1];
    const float* value = (const float*)d_in[2];
    const float* Wq = (const float*)d_in[3];
    const float* bq = (const float*)d_in[4];
    const float* Wk = (const float*)d_in[5];
    const float* bk = (const float*)d_in[6];
    const float* Wv = (const float*)d_in[7];
    const float* bv = (const float*)d_in[8];
    const float* Wo = (const float*)d_in[9];
    const float* bo = (const float*)d_in[10];
    const float* qmapW = (const float*)d_in[11];
    const float* qmapb = (const float*)d_in[12];
    const float* qw    = (const float*)d_in[13];
    const float* ph    = (const float*)d_in[14];
    const float* es    = (const float*)d_in[15];

    float* out  = (float*)d_out;
    float* out2 = out + (size_t)MM * DDIM;

    {   // pre: round inputs, transpose+round weights
        size_t n = (size_t)3 * MM * DDIM / 4;
        around_kernel<<<(unsigned)((n + 255) / 256), 256>>>(query, key, value);
        wtrans_kernel<<<dim3(DDIM / 32, DDIM / 32, 4), dim3(32, 8)>>>(Wq, Wk, Wv, Wo);
    }
    proj_kernel<<<dim3(DDIM / 128, MM / 128, 3), 256>>>(bq, bk, bv);
    {   // qfeat also zero-fills d_out (out + out2)
        int nrows = 2 * BHn * SS;
        qfeat_kernel<<<nrows / 8, 256>>>(qmapW, qmapb, qw, ph, es, out);
    }
    {
        size_t smem = (size_t)64 * PROW * 4 + (size_t)2 * 64 * VPITCH * 4; // 232448
        cudaFuncSetAttribute(attn_kernel,
                             cudaFuncAttributeMaxDynamicSharedMemorySize, (int)smem);
        attn_kernel<<<dim3(SS / 64, BHn), ATHREADS, smem>>>(es, out2);
    }
    outproj_kernel<<<dim3(DDIM / 128, MM / 128, 3), 256>>>(bo, out);
}